// round 1
// baseline (speedup 1.0000x reference)
#include <cuda_runtime.h>
#include <cuda_bf16.h>
#include <math.h>
#include <math_constants.h>

// Problem constants
#define TT   2048
#define HID  2048
#define NH   16
#define NKV  8
#define DH   128
#define QKVW ((NH + 2 * NKV) * DH)   // 4096
#define EPS  1e-6f

// Scratch (allocation-free rule: __device__ globals)
__device__ float g_qkv[(size_t)TT * QKVW];      // 32 MB: [T][4096] = q(2048) | k(1024) | v(1024)
__device__ float g_attn[(size_t)TT * NH * DH];  // 16 MB: [T][2048]

// ---------------------------------------------------------------------------
// SGEMM: C[M,N] = A[M,K] @ B[K,N], all row-major, fp32.
// 128x128 block tile, BK=8, 256 threads, 8x8 per-thread register tile.
// Requires M%128==0, N%128==0, K%8==0 (holds: 2048/4096).
// ---------------------------------------------------------------------------
#define GBM 128
#define GBN 128
#define GBK 8

__global__ __launch_bounds__(256) void sgemm_kernel(
    int M, int N, int K,
    const float* __restrict__ A, const float* __restrict__ B,
    float* __restrict__ C)
{
    __shared__ float As[GBK][GBM];   // transposed A tile
    __shared__ float Bs[GBK][GBN];

    const int tid = threadIdx.x;
    const int tx  = tid & 15;        // 0..15 -> cols tx*8
    const int ty  = tid >> 4;        // 0..15 -> rows ty*8
    const int bm  = blockIdx.y * GBM;
    const int bn  = blockIdx.x * GBN;

    // A load map: 128x8 tile = 256 float4; 1 per thread
    const int aRow = tid >> 1;           // 0..127
    const int aCol = (tid & 1) << 2;     // 0 or 4
    // B load map: 8x128 tile = 256 float4
    const int bRow = tid >> 5;           // 0..7
    const int bCol = (tid & 31) << 2;    // 0..124

    float acc[8][8];
#pragma unroll
    for (int i = 0; i < 8; i++)
#pragma unroll
        for (int j = 0; j < 8; j++) acc[i][j] = 0.f;

    for (int k0 = 0; k0 < K; k0 += GBK) {
        float4 a4 = *(const float4*)(A + (size_t)(bm + aRow) * K + k0 + aCol);
        As[aCol + 0][aRow] = a4.x;
        As[aCol + 1][aRow] = a4.y;
        As[aCol + 2][aRow] = a4.z;
        As[aCol + 3][aRow] = a4.w;
        *(float4*)&Bs[bRow][bCol] =
            *(const float4*)(B + (size_t)(k0 + bRow) * N + bn + bCol);
        __syncthreads();

#pragma unroll
        for (int kk = 0; kk < GBK; kk++) {
            float ra[8], rb[8];
            *(float4*)&ra[0] = *(float4*)&As[kk][ty * 8];
            *(float4*)&ra[4] = *(float4*)&As[kk][ty * 8 + 4];
            *(float4*)&rb[0] = *(float4*)&Bs[kk][tx * 8];
            *(float4*)&rb[4] = *(float4*)&Bs[kk][tx * 8 + 4];
#pragma unroll
            for (int i = 0; i < 8; i++)
#pragma unroll
                for (int j = 0; j < 8; j++)
                    acc[i][j] += ra[i] * rb[j];
        }
        __syncthreads();
    }

#pragma unroll
    for (int i = 0; i < 8; i++)
#pragma unroll
        for (int j = 0; j < 8; j += 4) {
            float4 v = make_float4(acc[i][j], acc[i][j + 1], acc[i][j + 2], acc[i][j + 3]);
            *(float4*)(C + (size_t)(bm + ty * 8 + i) * N + bn + tx * 8 + j) = v;
        }
}

// ---------------------------------------------------------------------------
// Per-head RMSNorm + neox RoPE, in-place on q and k slices of g_qkv.
// grid = (NH+NKV, T), block = 128 threads (one per dim element).
// ---------------------------------------------------------------------------
__global__ __launch_bounds__(128) void norm_rope_kernel(
    const int* __restrict__ positions,
    const float* __restrict__ qw, const float* __restrict__ kw,
    float* __restrict__ qkv)
{
    const int t = blockIdx.y;
    const int h = blockIdx.x;    // 0..15 = q heads, 16..23 = k heads (contiguous layout)
    const int d = threadIdx.x;

    float* ptr = qkv + (size_t)t * QKVW + h * DH;
    const float* w = (h < NH) ? qw : kw;

    float x = ptr[d];
    float ss = x * x;
#pragma unroll
    for (int o = 16; o > 0; o >>= 1) ss += __shfl_xor_sync(0xffffffffu, ss, o);

    __shared__ float wsum[4];
    __shared__ float xs[DH];
    if ((d & 31) == 0) wsum[d >> 5] = ss;
    __syncthreads();
    float tot = wsum[0] + wsum[1] + wsum[2] + wsum[3];
    float xn = x * rsqrtf(tot * (1.f / DH) + EPS) * w[d];
    xs[d] = xn;
    __syncthreads();

    if (d < 64) {
        float x1 = xs[d], x2 = xs[d + 64];
        float pos = (float)positions[t];
        float inv_freq = powf(10000.f, -(float)d * (1.f / 64.f));  // accurate path
        float ang = pos * inv_freq;
        float sv, cv;
        sincosf(ang, &sv, &cv);
        ptr[d]      = x1 * cv - x2 * sv;
        ptr[d + 64] = x2 * cv + x1 * sv;
    }
}

// ---------------------------------------------------------------------------
// Flash-style causal GQA attention, fp32.
// One block per (head, q-tile of 128 rows). 256 threads.
// Streams 64-key tiles with online softmax. O accumulated in registers.
// ---------------------------------------------------------------------------
#define AT_BM 128
#define AT_BN 64

struct AttnSmem {
    float Qs[DH][AT_BM + 4];     // [d][row], Q pre-scaled
    float Ks[DH][AT_BN + 4];     // [d][key]
    float Vs[AT_BN][DH];         // [key][d]
    float Ps[AT_BN][AT_BM + 4];  // [key][row] scores -> probs
    float row_m[AT_BM];
    float row_l[AT_BM];
    float row_c[AT_BM];
};

__global__ __launch_bounds__(256, 1) void attn_kernel(
    const float* __restrict__ qkv, float* __restrict__ out)
{
    extern __shared__ float smem_raw[];
    AttnSmem& s = *(AttnSmem*)smem_raw;

    const int h   = blockIdx.x;                          // 0..15
    const int m0  = (gridDim.y - 1 - blockIdx.y) * AT_BM; // heavy diagonal blocks first
    const int kvh = h >> 1;                               // G = NH/NKV = 2
    const int tid = threadIdx.x;
    const float scale = 0.08838834764831845f;             // 1/sqrt(128)

    const float* qbase = qkv + h * DH;
    const float* kbase = qkv + NH * DH + kvh * DH;              // +2048
    const float* vbase = qkv + (NH + NKV) * DH + kvh * DH;      // +3072

    // Load Q tile (scaled), transposed to [d][row]
    for (int u = tid; u < AT_BM * 32; u += 256) {
        int row = u >> 5;
        int d   = (u & 31) << 2;
        float4 q4 = *(const float4*)(qbase + (size_t)(m0 + row) * QKVW + d);
        s.Qs[d + 0][row] = q4.x * scale;
        s.Qs[d + 1][row] = q4.y * scale;
        s.Qs[d + 2][row] = q4.z * scale;
        s.Qs[d + 3][row] = q4.w * scale;
    }
    if (tid < AT_BM) { s.row_m[tid] = -CUDART_INF_F; s.row_l[tid] = 0.f; }

    float accO[8][8];
#pragma unroll
    for (int i = 0; i < 8; i++)
#pragma unroll
        for (int j = 0; j < 8; j++) accO[i][j] = 0.f;

    const int tx = tid & 15;   // S cols tx*4 ; O cols tx*8
    const int ty = tid >> 4;   // rows ty*8
    const int n_tiles = (m0 + AT_BM) / AT_BN;  // m0/64 + 2

    for (int tile = 0; tile < n_tiles; tile++) {
        const int n0 = tile * AT_BN;
        __syncthreads();  // previous iteration consumers done (also covers Q load)

        // Load K (transposed) + V tile
        for (int u = tid; u < AT_BN * 32; u += 256) {
            int key = u >> 5;
            int d   = (u & 31) << 2;
            float4 k4 = *(const float4*)(kbase + (size_t)(n0 + key) * QKVW + d);
            s.Ks[d + 0][key] = k4.x;
            s.Ks[d + 1][key] = k4.y;
            s.Ks[d + 2][key] = k4.z;
            s.Ks[d + 3][key] = k4.w;
            *(float4*)&s.Vs[key][d] =
                *(const float4*)(vbase + (size_t)(n0 + key) * QKVW + d);
        }
        __syncthreads();

        // S = Q @ K^T  (each thread: rows ty*8..+7, cols tx*4..+3)
        float accS[8][4];
#pragma unroll
        for (int i = 0; i < 8; i++)
#pragma unroll
            for (int j = 0; j < 4; j++) accS[i][j] = 0.f;

#pragma unroll 4
        for (int kk = 0; kk < DH; kk++) {
            float ra[8], rb[4];
            *(float4*)&ra[0] = *(float4*)&s.Qs[kk][ty * 8];
            *(float4*)&ra[4] = *(float4*)&s.Qs[kk][ty * 8 + 4];
            *(float4*)&rb[0] = *(float4*)&s.Ks[kk][tx * 4];
#pragma unroll
            for (int i = 0; i < 8; i++)
#pragma unroll
                for (int j = 0; j < 4; j++)
                    accS[i][j] += ra[i] * rb[j];
        }

        // Causal mask + store transposed [key][row]
        const bool need_mask = (n0 + AT_BN - 1 > m0);
#pragma unroll
        for (int i = 0; i < 8; i++) {
            int row = ty * 8 + i;
#pragma unroll
            for (int j = 0; j < 4; j++) {
                int col = tx * 4 + j;
                float v = accS[i][j];
                if (need_mask && (n0 + col > m0 + row)) v = -CUDART_INF_F;
                s.Ps[col][row] = v;
            }
        }
        __syncthreads();

        // Online softmax per row (128 threads)
        if (tid < AT_BM) {
            const int r = tid;
            float m_old = s.row_m[r];
            float m_new = m_old;
#pragma unroll 8
            for (int j = 0; j < AT_BN; j++) m_new = fmaxf(m_new, s.Ps[j][r]);
            float corr = __expf(m_old - m_new);   // exp(-inf)=0 on first tile
            float sum = 0.f;
#pragma unroll 8
            for (int j = 0; j < AT_BN; j++) {
                float p = __expf(s.Ps[j][r] - m_new);
                s.Ps[j][r] = p;
                sum += p;
            }
            s.row_m[r] = m_new;
            s.row_l[r] = s.row_l[r] * corr + sum;
            s.row_c[r] = corr;
        }
        __syncthreads();

        // O = O * corr + P @ V   (each thread: rows ty*8..+7, cols tx*8..+7)
        float c[8];
#pragma unroll
        for (int i = 0; i < 8; i++) c[i] = s.row_c[ty * 8 + i];
#pragma unroll
        for (int i = 0; i < 8; i++)
#pragma unroll
            for (int j = 0; j < 8; j++) accO[i][j] *= c[i];

#pragma unroll 2
        for (int kk = 0; kk < AT_BN; kk++) {
            float pa[8], vb[8];
            *(float4*)&pa[0] = *(float4*)&s.Ps[kk][ty * 8];
            *(float4*)&pa[4] = *(float4*)&s.Ps[kk][ty * 8 + 4];
            *(float4*)&vb[0] = *(float4*)&s.Vs[kk][tx * 8];
            *(float4*)&vb[4] = *(float4*)&s.Vs[kk][tx * 8 + 4];
#pragma unroll
            for (int i = 0; i < 8; i++)
#pragma unroll
                for (int j = 0; j < 8; j++)
                    accO[i][j] += pa[i] * vb[j];
        }
    }

    // Normalize and write out: out[t][h*128 + d]
    float invl[8];
#pragma unroll
    for (int i = 0; i < 8; i++) invl[i] = 1.f / s.row_l[ty * 8 + i];
#pragma unroll
    for (int i = 0; i < 8; i++) {
        float4 o0 = make_float4(accO[i][0] * invl[i], accO[i][1] * invl[i],
                                accO[i][2] * invl[i], accO[i][3] * invl[i]);
        float4 o1 = make_float4(accO[i][4] * invl[i], accO[i][5] * invl[i],
                                accO[i][6] * invl[i], accO[i][7] * invl[i]);
        size_t off = (size_t)(m0 + ty * 8 + i) * (NH * DH) + h * DH + tx * 8;
        *(float4*)(out + off)     = o0;
        *(float4*)(out + off + 4) = o1;
    }
}

// ---------------------------------------------------------------------------
// Launch
// ---------------------------------------------------------------------------
extern "C" void kernel_launch(void* const* d_in, const int* in_sizes, int n_in,
                              void* d_out, int out_size)
{
    const int*   positions = (const int*)d_in[0];
    const float* hidden    = (const float*)d_in[1];
    const float* w_qkv     = (const float*)d_in[2];
    const float* w_o       = (const float*)d_in[3];
    const float* q_norm_w  = (const float*)d_in[4];
    const float* k_norm_w  = (const float*)d_in[5];
    float*       out       = (float*)d_out;

    float* qkv_ptr = nullptr;
    float* attn_ptr = nullptr;
    cudaGetSymbolAddress((void**)&qkv_ptr, g_qkv);
    cudaGetSymbolAddress((void**)&attn_ptr, g_attn);

    // 1. QKV projection: [T,HID] @ [HID,4096]
    {
        dim3 grid(QKVW / GBN, TT / GBM);
        sgemm_kernel<<<grid, 256>>>(TT, QKVW, HID, hidden, w_qkv, qkv_ptr);
    }

    // 2. RMSNorm + RoPE on q,k (in-place)
    {
        dim3 grid(NH + NKV, TT);
        norm_rope_kernel<<<grid, 128>>>(positions, q_norm_w, k_norm_w, qkv_ptr);
    }

    // 3. Causal GQA flash attention
    {
        static_assert(sizeof(AttnSmem) <= 224 * 1024, "smem");
        cudaFuncSetAttribute(attn_kernel,
                             cudaFuncAttributeMaxDynamicSharedMemorySize,
                             (int)sizeof(AttnSmem));
        dim3 grid(NH, TT / AT_BM);
        attn_kernel<<<grid, 256, sizeof(AttnSmem)>>>(qkv_ptr, attn_ptr);
    }

    // 4. Output projection: [T,2048] @ [2048,HID]
    {
        dim3 grid(HID / GBN, TT / GBM);
        sgemm_kernel<<<grid, 256>>>(TT, HID, NH * DH, attn_ptr, w_o, out);
    }
}